// round 1
// baseline (speedup 1.0000x reference)
#include <cuda_runtime.h>
#include <math.h>

// Problem constants
#define BB   8
#define LL   1024
#define SSZ  1024
#define HHN  8
#define DDIM 64
#define NQV  4
#define DIMV 16
#define BHN  (BB*HHN)

#define CTX_ELEMS (BB*LL*HHN*DDIM)          // 4194304 (context first in output)
#define PI_F 3.14159274101257324f

// Scratch statevectors (packed for f32x2 FMA)
// Q: [bh][l][k(16)][4] = {qr, qi, qi, -qr}
// K: [bh][k(16)][s][4] = {kr, kr, ki, ki}   (k-major for conflict-free staging)
__device__ float g_qsv[(size_t)BHN * LL * 64];
__device__ float g_ksv[(size_t)BHN * SSZ * 64];

// ---------- f32x2 helpers ----------
typedef unsigned long long u64;

__device__ __forceinline__ u64 pk2(float x, float y) {
    u64 r; asm("mov.b64 %0, {%1, %2};" : "=l"(r) : "f"(x), "f"(y)); return r;
}
__device__ __forceinline__ void ffma2(u64& d, u64 a, u64 b) {
    asm("fma.rn.f32x2 %0, %1, %2, %0;" : "+l"(d) : "l"(a), "l"(b));
}
__device__ __forceinline__ float2 upk2(u64 v) {
    float2 r; asm("mov.b64 {%0, %1}, %2;" : "=f"(r.x), "=f"(r.y) : "l"(v)); return r;
}

// ======================================================================
// Encode kernel: angles -> 16-amplitude statevector, packed store.
// One thread per (bh, pos). 65536 threads per tensor.
// ======================================================================
__global__ void __launch_bounds__(256) encode_kernel(
    const float* __restrict__ x,     // [B, POS, H, D]
    const float* __restrict__ w,     // [NQ, D]
    const float* __restrict__ bias,  // [NQ]
    int isK)
{
    __shared__ float sw[NQV * DDIM];
    __shared__ float sb[NQV];
    int tid = threadIdx.x;
    if (tid < NQV * DDIM) sw[tid] = w[tid];
    if (tid < NQV) sb[tid] = bias[tid];
    __syncthreads();

    int n  = blockIdx.x * blockDim.x + tid;     // 0..65535
    int bh = n >> 10;
    int loc = n & 1023;
    int b = bh >> 3, h = bh & 7;

    const float* xr = x + (size_t)((b * 1024 + loc) * HHN + h) * DDIM;

    // angles
    float th[NQV];
#pragma unroll
    for (int j = 0; j < NQV; j++) th[j] = sb[j];
#pragma unroll 4
    for (int d = 0; d < DDIM; d += 4) {
        float4 xv = *(const float4*)(xr + d);
#pragma unroll
        for (int j = 0; j < NQV; j++) {
            th[j] += xv.x * sw[j * DDIM + d]     + xv.y * sw[j * DDIM + d + 1]
                   + xv.z * sw[j * DDIM + d + 2] + xv.w * sw[j * DDIM + d + 3];
        }
    }
#pragma unroll
    for (int j = 0; j < NQV; j++) th[j] = tanhf(th[j]) * PI_F;

    float bt[3];
#pragma unroll
    for (int p = 0; p < 3; p++) bt[p] = th[p] * th[p + 1];

    // per-basis-state phase: phi[d] = -0.5 * arg[d]
    float co[16], si[16];
#pragma unroll
    for (int d = 0; d < 16; d++) {
        float a = 0.f;
        a += ((d >> 3) & 1) ? -th[0] : th[0];
        a += ((d >> 2) & 1) ? -th[1] : th[1];
        a += ((d >> 1) & 1) ? -th[2] : th[2];
        a += ( d       & 1) ? -th[3] : th[3];
        a += (((d >> 3) ^ (d >> 2)) & 1) ? -bt[0] : bt[0];
        a += (((d >> 2) ^ (d >> 1)) & 1) ? -bt[1] : bt[1];
        a += (((d >> 1) ^  d      ) & 1) ? -bt[2] : bt[2];
        float ph = -0.5f * a;
        sincosf(ph, &si[d], &co[d]);
    }

    // layer1 state (times 1/4 folded later) = (co, si); FWHT (H^{x4} times 4)
    float re[16], im[16];
#pragma unroll
    for (int d = 0; d < 16; d++) { re[d] = co[d]; im[d] = si[d]; }
#pragma unroll
    for (int hs = 1; hs < 16; hs <<= 1) {
#pragma unroll
        for (int i = 0; i < 16; i++) {
            if ((i & hs) == 0) {
                int j2 = i | hs;
                float ar = re[i], ai = im[i], br = re[j2], bi = im[j2];
                re[i] = ar + br;  im[i] = ai + bi;
                re[j2] = ar - br; im[j2] = ai - bi;
            }
        }
    }

    // second diagonal + 1/16 scaling, packed stores
    if (!isK) {
        float4* outq = (float4*)g_qsv + (size_t)n * 16;
#pragma unroll
        for (int d = 0; d < 16; d++) {
            float tr = re[d] * 0.0625f, ti = im[d] * 0.0625f;
            float vr = tr * co[d] - ti * si[d];
            float vi = tr * si[d] + ti * co[d];
            outq[d] = make_float4(vr, vi, vi, -vr);
        }
    } else {
        float4* outk = (float4*)g_ksv;
#pragma unroll
        for (int d = 0; d < 16; d++) {
            float tr = re[d] * 0.0625f, ti = im[d] * 0.0625f;
            float vr = tr * co[d] - ti * si[d];
            float vi = tr * si[d] + ti * co[d];
            outk[(size_t)(bh * 16 + d) * 1024 + loc] = make_float4(vr, vr, vi, vi);
        }
    }
}

// ======================================================================
// Main fused kernel: per (bh, 32-row L-tile)
//   phase A: scores (raw |fid|^2) for 32 x 1024 into smem  (f32x2 FMA)
//   phase B: rowsums -> weights streamed to d_out
//   phase C: context = scores @ V scaled by 1/rowsum
// ======================================================================
#define TL 32
#define SCROW 1028            // padded row stride (floats)
#define SMEM_FLOATS (TL*SCROW + TL*64 + 128*64)
#define SMEM_BYTES  (SMEM_FLOATS * 4)

__global__ void __launch_bounds__(256, 1) attn_main(
    const float* __restrict__ values,   // [B,S,H,D]
    float* __restrict__ out)            // [context | weights]
{
    extern __shared__ float smem[];
    float* sc  = smem;                      // [TL][SCROW]
    float* qsm = smem + TL * SCROW;         // [TL][64]  packed q tile
    float* ksm = qsm + TL * 64;             // [16][128][4] k chunk / [128][64] v chunk
    __shared__ float sinv[TL];

    const int bh = blockIdx.y;
    const int l0 = blockIdx.x * TL;
    const int b = bh >> 3, h = bh & 7;
    const int tid = threadIdx.x;

    // stage Q tile (512 float4, coalesced)
    {
        const float4* qg = (const float4*)g_qsv + (size_t)(bh * 1024 + l0) * 16;
        float4* q4 = (float4*)qsm;
        for (int i = tid; i < TL * 16; i += 256) q4[i] = qg[i];
    }

    const int lg = tid >> 5;    // warp id = l-group (4 rows)
    const int sg = tid & 31;    // s lane

    // ---- phase A: scores ----
    for (int s0 = 0; s0 < 1024; s0 += 128) {
        __syncthreads();
        {   // stage K chunk: [k][128] float4, both sides coalesced/conflict-free
            const float4* kg = (const float4*)g_ksv + (size_t)bh * 16 * 1024;
            float4* k4 = (float4*)ksm;
            for (int i = tid; i < 2048; i += 256) {
                int kk = i >> 7, s = i & 127;
                k4[i] = kg[kk * 1024 + s0 + s];
            }
        }
        __syncthreads();

        u64 acc[4][4];
#pragma unroll
        for (int il = 0; il < 4; il++)
#pragma unroll
            for (int is = 0; is < 4; is++) acc[il][is] = 0ull;

        const ulonglong2* q2 = (const ulonglong2*)qsm;
        const ulonglong2* k2 = (const ulonglong2*)ksm;
#pragma unroll
        for (int k = 0; k < 16; k++) {
            ulonglong2 kv[4];
#pragma unroll
            for (int is = 0; is < 4; is++) kv[is] = k2[k * 128 + sg + 32 * is];
#pragma unroll
            for (int il = 0; il < 4; il++) {
                ulonglong2 qv = q2[(lg * 4 + il) * 16 + k];
#pragma unroll
                for (int is = 0; is < 4; is++) {
                    ffma2(acc[il][is], qv.x, kv[is].x);   // (qr,qi)*(kr,kr)
                    ffma2(acc[il][is], qv.y, kv[is].y);   // (qi,-qr)*(ki,ki)
                }
            }
        }
#pragma unroll
        for (int il = 0; il < 4; il++)
#pragma unroll
            for (int is = 0; is < 4; is++) {
                float2 f = upk2(acc[il][is]);
                sc[(lg * 4 + il) * SCROW + s0 + sg + 32 * is] = f.x * f.x + f.y * f.y;
            }
    }
    __syncthreads();

    // ---- rowsums ----
    {
        int w = tid >> 5, lane = tid & 31;
#pragma unroll
        for (int r = 0; r < 4; r++) {
            int l = w * 4 + r;
            float s = 0.f;
            for (int i = lane; i < 1024; i += 32) s += sc[l * SCROW + i];
#pragma unroll
            for (int o = 16; o; o >>= 1) s += __shfl_xor_sync(0xFFFFFFFFu, s, o);
            if (lane == 0) sinv[l] = 1.0f / (s + 1e-6f);
        }
    }
    __syncthreads();

    // ---- phase B: weights ----
    {
        float4* wout = (float4*)(out + (size_t)CTX_ELEMS + ((size_t)bh * 1024 + l0) * 1024);
        for (int i = tid; i < TL * 256; i += 256) {
            int l = i >> 8, s4 = i & 255;
            float4 v = ((const float4*)(sc + l * SCROW))[s4];
            float iv = sinv[l];
            v.x *= iv; v.y *= iv; v.z *= iv; v.w *= iv;
            wout[(size_t)l * 256 + s4] = v;
        }
    }

    // ---- phase C: context ----
    const int dg = tid & 15;    // 16 d-groups of 4
    const int lq = tid >> 4;    // 16 l-groups of 2
    u64 c0[2] = {0ull, 0ull}, c1[2] = {0ull, 0ull};

    for (int s0 = 0; s0 < 1024; s0 += 128) {
        __syncthreads();
        {   // stage V chunk [128][64] floats
            const float4* vg = (const float4*)values;
            float4* v4 = (float4*)ksm;
            for (int i = tid; i < 2048; i += 256) {
                int s = i >> 4, dq = i & 15;
                v4[i] = vg[(size_t)((b * 1024 + s0 + s) * HHN + h) * 16 + dq];
            }
        }
        __syncthreads();
        const ulonglong2* vv = (const ulonglong2*)ksm;
#pragma unroll 4
        for (int s = 0; s < 128; s++) {
            ulonglong2 v2 = vv[s * 16 + dg];
#pragma unroll
            for (int il = 0; il < 2; il++) {
                float wt = sc[(lq * 2 + il) * SCROW + s0 + s];
                u64 w2 = pk2(wt, wt);
                ffma2(c0[il], w2, v2.x);
                ffma2(c1[il], w2, v2.y);
            }
        }
    }

#pragma unroll
    for (int il = 0; il < 2; il++) {
        int l = lq * 2 + il;
        float iv = sinv[l];
        float2 a = upk2(c0[il]), bb = upk2(c1[il]);
        float4 r = make_float4(a.x * iv, a.y * iv, bb.x * iv, bb.y * iv);
        ((float4*)out)[(size_t)((b * 1024 + (l0 + l)) * HHN + h) * 16 + dg] = r;
    }
}

// ======================================================================
extern "C" void kernel_launch(void* const* d_in, const int* in_sizes, int n_in,
                              void* d_out, int out_size)
{
    (void)in_sizes; (void)n_in; (void)out_size;
    const float* q  = (const float*)d_in[0];
    const float* k  = (const float*)d_in[1];
    const float* v  = (const float*)d_in[2];
    const float* wq = (const float*)d_in[3];
    const float* bq = (const float*)d_in[4];
    const float* wk = (const float*)d_in[5];
    const float* bk = (const float*)d_in[6];
    float* out = (float*)d_out;

    cudaFuncSetAttribute(attn_main, cudaFuncAttributeMaxDynamicSharedMemorySize, SMEM_BYTES);

    encode_kernel<<<256, 256>>>(q, wq, bq, 0);
    encode_kernel<<<256, 256>>>(k, wk, bk, 1);
    attn_main<<<dim3(LL / TL, BHN), 256, SMEM_BYTES>>>(v, out);
}